// round 4
// baseline (speedup 1.0000x reference)
#include <cuda_runtime.h>
#include <cstdint>

// ============================================================================
// out[M,N] = float( sum_k x[m,k]*w[n,k] ) + rint(bias[n])
// M=8192, N=4096, K=4096.
// KEY FINDING (R3): harness delivers the int8 tensors widened to int32.
// Stage 1: pack int32 -> int8 into __device__ scratch (exact, values fit s8).
// Stage 2: mma.sync m16n8k32 s8 IMMA GEMM, cp.async 3-stage pipeline,
//          SW128 swizzle, ldmatrix.x4 operand loads.
// CTA tile 128x128, K staged 128B; 8 warps, warp tile 64x32.
// ============================================================================

#define K_DIM 4096
#define N_DIM 4096
#define M_DIM 8192
#define M_TILE 128
#define N_TILE 128
#define K_TILE 128
#define STAGES 3
#define K_ITERS (K_DIM / K_TILE)        // 32
#define NTHREADS 256

#define A_STAGE_BYTES (M_TILE * K_TILE) // 16384
#define B_STAGE_BYTES (N_TILE * K_TILE) // 16384
#define SM_A 0
#define SM_B (STAGES * A_STAGE_BYTES)               // 49152
#define SM_RBIAS (SM_B + STAGES * B_STAGE_BYTES)    // 98304
#define SMEM_TOTAL (SM_RBIAS + N_TILE * 4)          // 98816

// -------- packed int8 scratch (device globals: allocation-free) -----------
__device__ int8_t g_xpack[(size_t)M_DIM * K_DIM];   // 32 MB
__device__ int8_t g_wpack[(size_t)N_DIM * K_DIM];   // 16 MB

// ---------------------------------------------------------------- helpers
__device__ __forceinline__ uint32_t smem_u32(const void* p) {
    uint32_t a;
    asm("{ .reg .u64 t; cvta.to.shared.u64 t, %1; cvt.u32.u64 %0, t; }"
        : "=r"(a) : "l"(p));
    return a;
}

__device__ __forceinline__ void cp16(uint32_t smem_dst, const void* gmem_src) {
    asm volatile("cp.async.cg.shared.global [%0], [%1], 16;"
                 :: "r"(smem_dst), "l"(gmem_src));
}
__device__ __forceinline__ void cp_commit() {
    asm volatile("cp.async.commit_group;" ::: "memory");
}
__device__ __forceinline__ void cp_wait1() {
    asm volatile("cp.async.wait_group 1;" ::: "memory");
}
__device__ __forceinline__ void cp_wait0() {
    asm volatile("cp.async.wait_group 0;" ::: "memory");
}

__device__ __forceinline__ void ldsm4(uint32_t r[4], uint32_t addr) {
    asm volatile("ldmatrix.sync.aligned.m8n8.x4.shared.b16 {%0,%1,%2,%3}, [%4];"
                 : "=r"(r[0]), "=r"(r[1]), "=r"(r[2]), "=r"(r[3])
                 : "r"(addr));
}

__device__ __forceinline__ void mma_s8(int d[4], const uint32_t a[4],
                                       uint32_t b0, uint32_t b1) {
    asm volatile(
        "mma.sync.aligned.m16n8k32.row.col.s32.s8.s8.s32 "
        "{%0,%1,%2,%3}, {%4,%5,%6,%7}, {%8,%9}, {%0,%1,%2,%3};"
        : "+r"(d[0]), "+r"(d[1]), "+r"(d[2]), "+r"(d[3])
        : "r"(a[0]), "r"(a[1]), "r"(a[2]), "r"(a[3]), "r"(b0), "r"(b1));
}

// SW128 swizzle for a [row][128B] tile: chunk c (16B units) -> c ^ (row & 7)
__device__ __forceinline__ uint32_t sw_off(int row, int c) {
    return (uint32_t)(row * 128 + ((c ^ (row & 7)) << 4));
}

// ---------------------------------------------------------------- pack
// Each thread: read 4x int4 (16 int32 = 64B), write one uint4 (16 int8).
__global__ void __launch_bounds__(256)
pack_s32_to_s8(const int* __restrict__ src, int8_t* __restrict__ dst, int n16) {
    int i = blockIdx.x * blockDim.x + threadIdx.x;
    if (i >= n16) return;
    const int4* s = reinterpret_cast<const int4*>(src) + (size_t)i * 4;
    uint32_t p[4];
    #pragma unroll
    for (int j = 0; j < 4; j++) {
        int4 v = __ldg(&s[j]);
        p[j] = (v.x & 0xFF) | ((v.y & 0xFF) << 8) |
               ((v.z & 0xFF) << 16) | ((uint32_t)v.w << 24);
    }
    reinterpret_cast<uint4*>(dst)[i] = make_uint4(p[0], p[1], p[2], p[3]);
}

// ---------------------------------------------------------------- GEMM
__global__ void __launch_bounds__(NTHREADS, 2)
w8a8_imma_kernel(const float* __restrict__ bias, float* __restrict__ out) {
    extern __shared__ char smem[];
    const uint32_t sb = smem_u32(smem);
    const int tid  = threadIdx.x;
    const int wid  = tid >> 5;
    const int lane = tid & 31;

    const int n0 = blockIdx.x * N_TILE;
    const int m0 = blockIdx.y * M_TILE;

    float* rbias = reinterpret_cast<float*>(smem + SM_RBIAS);
    for (int j = tid; j < N_TILE; j += NTHREADS)
        rbias[j] = rintf(__ldg(&bias[n0 + j]));

    const int8_t* Ab = g_xpack + (size_t)m0 * K_DIM;
    const int8_t* Wb = g_wpack + (size_t)n0 * K_DIM;

    // stage load: 1024 16B chunks per operand; thread g = tid + i*256
    #define LOAD_STAGE(ks_) do {                                              \
        const int s_ = (ks_) % STAGES;                                        \
        const uint32_t sa_ = sb + SM_A + s_ * A_STAGE_BYTES;                  \
        const uint32_t sw_ = sb + SM_B + s_ * B_STAGE_BYTES;                  \
        const int koff_ = (ks_) * K_TILE;                                     \
        _Pragma("unroll")                                                     \
        for (int i_ = 0; i_ < 4; i_++) {                                      \
            int g_ = tid + i_ * 256;                                          \
            int row_ = g_ >> 3, c_ = g_ & 7;                                  \
            cp16(sa_ + sw_off(row_, c_),                                      \
                 Ab + (size_t)row_ * K_DIM + koff_ + c_ * 16);                \
        }                                                                     \
        _Pragma("unroll")                                                     \
        for (int i_ = 0; i_ < 4; i_++) {                                      \
            int g_ = tid + i_ * 256;                                          \
            int row_ = g_ >> 3, c_ = g_ & 7;                                  \
            cp16(sw_ + sw_off(row_, c_),                                      \
                 Wb + (size_t)row_ * K_DIM + koff_ + c_ * 16);                \
        }                                                                     \
        cp_commit();                                                          \
    } while (0)

    #pragma unroll
    for (int ks = 0; ks < STAGES - 1; ks++) LOAD_STAGE(ks);

    // warp tile: 64(M) x 32(N);  warps: 2 in M x 4 in N
    const int wm = (wid & 1) * 64;
    const int wn = (wid >> 1) * 32;

    int acc[4][4][4];
    #pragma unroll
    for (int mi = 0; mi < 4; mi++)
        #pragma unroll
        for (int ni = 0; ni < 4; ni++)
            #pragma unroll
            for (int r = 0; r < 4; r++) acc[mi][ni][r] = 0;

    // ldmatrix.x4 lane addressing: lanes 0-15 -> rows (base..base+15) at
    // chunk 2kk; lanes 16-31 -> same rows at chunk 2kk+1.
    // Matrix order then delivers exactly the m16n8k32 s8 A/B fragments.
    const int lrow = lane & 15;
    const int lchunk = lane >> 4;

    for (int ks = 0; ks < K_ITERS; ks++) {
        if (ks == K_ITERS - 1) cp_wait0(); else cp_wait1();
        __syncthreads();
        if (ks + STAGES - 1 < K_ITERS) LOAD_STAGE(ks + STAGES - 1);

        const int s = ks % STAGES;
        const uint32_t sa = sb + SM_A + s * A_STAGE_BYTES;
        const uint32_t sw = sb + SM_B + s * B_STAGE_BYTES;

        #pragma unroll
        for (int kk = 0; kk < 4; kk++) {              // 4 x k32 per stage
            const int c = kk * 2 + lchunk;
            uint32_t afr[4][4];
            #pragma unroll
            for (int mi = 0; mi < 4; mi++) {
                int row = wm + mi * 16 + lrow;
                ldsm4(afr[mi], sa + sw_off(row, c));
            }
            uint32_t bfr[2][4];
            #pragma unroll
            for (int nj = 0; nj < 2; nj++) {
                int row = wn + nj * 16 + lrow;
                ldsm4(bfr[nj], sw + sw_off(row, c));
            }
            #pragma unroll
            for (int mi = 0; mi < 4; mi++)
                #pragma unroll
                for (int ni = 0; ni < 4; ni++)
                    mma_s8(acc[mi][ni], afr[mi],
                           bfr[ni >> 1][ni & 1], bfr[ni >> 1][(ni & 1) + 2]);
        }
    }

    // epilogue: c0,c1 at (row=lane>>2, col=(lane&3)*2+{0,1}); c2,c3 at row+8
    const int erow = lane >> 2;
    const int ecol = (lane & 3) * 2;
    #pragma unroll
    for (int mi = 0; mi < 4; mi++) {
        #pragma unroll
        for (int ni = 0; ni < 4; ni++) {
            const int gc = wn + ni * 8 + ecol;
            const float b0 = rbias[gc], b1 = rbias[gc + 1];
            {
                const int gr = m0 + wm + mi * 16 + erow;
                float2 v;
                v.x = (float)acc[mi][ni][0] + b0;
                v.y = (float)acc[mi][ni][1] + b1;
                *reinterpret_cast<float2*>(out + (size_t)gr * N_DIM + n0 + gc) = v;
            }
            {
                const int gr = m0 + wm + mi * 16 + 8 + erow;
                float2 v;
                v.x = (float)acc[mi][ni][2] + b0;
                v.y = (float)acc[mi][ni][3] + b1;
                *reinterpret_cast<float2*>(out + (size_t)gr * N_DIM + n0 + gc) = v;
            }
        }
    }
}

// ---------------------------------------------------------------- launch
extern "C" void kernel_launch(void* const* d_in, const int* in_sizes, int n_in,
                              void* d_out, int out_size) {
    // x = largest input, bias = smallest, weight = remaining.
    int xi = 0, bi = 0;
    for (int i = 1; i < n_in; i++) {
        if (in_sizes[i] > in_sizes[xi]) xi = i;
        if (in_sizes[i] < in_sizes[bi]) bi = i;
    }
    int wi = 3 - xi - bi;

    // R3 finding: int8 tensors are delivered widened to int32.
    const int*   x32  = (const int*)d_in[xi];
    const int*   w32  = (const int*)d_in[wi];
    const float* bias = (const float*)d_in[bi];
    float* out = (float*)d_out;

    int8_t* xp = nullptr; cudaGetSymbolAddress((void**)&xp, g_xpack);
    int8_t* wp = nullptr; cudaGetSymbolAddress((void**)&wp, g_wpack);

    // pack int32 -> int8 (exact; values in [-127,126])
    {
        int n16x = (M_DIM * K_DIM) / 16;   // 2,097,152
        int n16w = (N_DIM * K_DIM) / 16;   // 1,048,576
        pack_s32_to_s8<<<(n16x + 255) / 256, 256>>>(x32, xp, n16x);
        pack_s32_to_s8<<<(n16w + 255) / 256, 256>>>(w32, wp, n16w);
    }

    cudaFuncSetAttribute(w8a8_imma_kernel,
                         cudaFuncAttributeMaxDynamicSharedMemorySize, SMEM_TOTAL);

    dim3 grid(N_DIM / N_TILE, M_DIM / M_TILE);     // (32, 64)
    w8a8_imma_kernel<<<grid, NTHREADS, SMEM_TOTAL>>>(bias, out);
}